// round 4
// baseline (speedup 1.0000x reference)
#include <cuda_runtime.h>
#include <cuda_bf16.h>
#include <math.h>

// Problem constants (DEPTH=2, but reference only returns last layer's output
// computed from the ORIGINAL x, so we evaluate ONLY layer index 1).
#define BATCH 2
#define SEQ   2048
#define DIM   256
#define MLPD  1024
#define HEADS 8
#define HD    32
#define ROWS  (BATCH*SEQ)          // 4096
#define LAYER 1                    // depth-1

// ------------------------- scratch (device globals) -------------------------
__device__ float g_y   [ROWS*DIM];    // ln1 out
__device__ float g_qkv [ROWS*3*DIM];  // qkv
__device__ float g_attn[ROWS*DIM];    // attention output (pre O-proj)
__device__ float g_a   [ROWS*DIM];    // attn residual
__device__ float g_z   [ROWS*DIM];    // ln2 out
__device__ float g_h   [ROWS*MLPD];   // mlp hidden

// ------------------------------ LayerNorm -----------------------------------
// One block (256 threads) per row of 256 elements.
__global__ void ln_kernel(const float* __restrict__ x,
                          const float* __restrict__ gamma,
                          const float* __restrict__ beta,
                          float* __restrict__ y)
{
    int row = blockIdx.x;
    int tid = threadIdx.x;
    float v = x[(size_t)row * DIM + tid];

    float s = v, sq = v * v;
    #pragma unroll
    for (int o = 16; o; o >>= 1) {
        s  += __shfl_xor_sync(0xffffffffu, s,  o);
        sq += __shfl_xor_sync(0xffffffffu, sq, o);
    }
    __shared__ float red[2][8];
    int w = tid >> 5, l = tid & 31;
    if (l == 0) { red[0][w] = s; red[1][w] = sq; }
    __syncthreads();
    float st = 0.f, sqt = 0.f;
    #pragma unroll
    for (int i = 0; i < 8; i++) { st += red[0][i]; sqt += red[1][i]; }
    float mean = st * (1.0f / DIM);
    float var  = sqt * (1.0f / DIM) - mean * mean;
    float inv  = rsqrtf(var + 1e-5f);
    y[(size_t)row * DIM + tid] = (v - mean) * inv * gamma[tid] + beta[tid];
}

// --------------------------------- GEMM -------------------------------------
// C[M,N] = A[M,K] @ B[K,N] + bias[N]  (+ epilogue)
// EPI: 0 = bias only, 1 = bias + exact GELU, 2 = bias + residual add
// 64x64 block tile, 256 threads, 4x4 microtile, KT=16. M,N multiples of 64,
// K multiple of 16 (true for all four GEMMs here).
template <int EPI>
__global__ void gemm_kernel(const float* __restrict__ A,
                            const float* __restrict__ B,
                            const float* __restrict__ bias,
                            const float* __restrict__ res,
                            float* __restrict__ C,
                            int M, int N, int K)
{
    __shared__ float As[64][17];   // [m][k], padded
    __shared__ float Bs[16][64];   // [k][n], float4-readable

    int tid = threadIdx.x;
    int bm = blockIdx.y * 64;
    int bn = blockIdx.x * 64;

    float acc[4][4];
    #pragma unroll
    for (int i = 0; i < 4; i++)
        #pragma unroll
        for (int j = 0; j < 4; j++) acc[i][j] = 0.f;

    int tx = tid & 15, ty = tid >> 4;

    for (int k0 = 0; k0 < K; k0 += 16) {
        #pragma unroll
        for (int i = 0; i < 4; i++) {
            int li = tid + i * 256;
            int m = li >> 4, kk = li & 15;
            As[m][kk] = A[(size_t)(bm + m) * K + k0 + kk];
        }
        #pragma unroll
        for (int i = 0; i < 4; i++) {
            int li = tid + i * 256;
            int kk = li >> 6, n = li & 63;
            Bs[kk][n] = B[(size_t)(k0 + kk) * N + bn + n];
        }
        __syncthreads();

        #pragma unroll
        for (int kk = 0; kk < 16; kk++) {
            float4 b4 = *(const float4*)&Bs[kk][tx * 4];
            float bv[4] = { b4.x, b4.y, b4.z, b4.w };
            #pragma unroll
            for (int i = 0; i < 4; i++) {
                float av = As[ty * 4 + i][kk];
                #pragma unroll
                for (int j = 0; j < 4; j++) acc[i][j] += av * bv[j];
            }
        }
        __syncthreads();
    }

    #pragma unroll
    for (int i = 0; i < 4; i++) {
        int m = bm + ty * 4 + i;
        #pragma unroll
        for (int j = 0; j < 4; j++) {
            int n = bn + tx * 4 + j;
            float c = acc[i][j] + bias[n];
            if (EPI == 1) {
                // exact GELU: 0.5*x*(1+erf(x/sqrt(2)))
                c = 0.5f * c * (1.0f + erff(c * 0.7071067811865476f));
            } else if (EPI == 2) {
                c += res[(size_t)m * N + n];
            }
            C[(size_t)m * N + n] = c;
        }
    }
}

// ------------------------------ Attention -----------------------------------
// qkv layout: [b, n, comp(3), h(8), hd(32)]  (comp: 0=q, 1=k, 2=v)
// Flash-style online softmax. Block = 64 query rows of one (b,h).
// 256 threads: 4 threads per q-row; each owns 8 of 32 output dims.
#define TQ 64
#define TK 64
__global__ void attn_kernel(const float* __restrict__ qkv,
                            float* __restrict__ out)
{
    __shared__ float Qs[TQ][33];
    __shared__ float Ks[TK][33];
    __shared__ float Vs[TK][32];
    __shared__ float Ss[TQ][TK];

    int bh = blockIdx.y;
    int b  = bh >> 3;
    int h  = bh & 7;
    int qt = blockIdx.x;
    int tid = threadIdx.x;
    int r  = tid >> 2;   // q-row in tile
    int c4 = tid & 3;    // which quarter of dims / which j-phase
    const float scale = 0.17677669529663687f;  // 1/sqrt(32)

    for (int i = tid; i < TQ * 32; i += 256) {
        int row = i >> 5, d = i & 31;
        int n = qt * TQ + row;
        Qs[row][d] = qkv[((size_t)(b * SEQ + n)) * (3 * DIM) + h * HD + d];
    }
    __syncthreads();

    float qreg[32];
    #pragma unroll
    for (int d = 0; d < 32; d++) qreg[d] = Qs[r][d];

    float m_run = -1e30f, l_run = 0.f;
    float acc[8];
    #pragma unroll
    for (int i = 0; i < 8; i++) acc[i] = 0.f;

    for (int kt = 0; kt < SEQ / TK; kt++) {
        __syncthreads();  // previous iteration's Ss/Vs reads complete
        for (int i = tid; i < TK * 32; i += 256) {
            int row = i >> 5, d = i & 31;
            int n = kt * TK + row;
            size_t base = ((size_t)(b * SEQ + n)) * (3 * DIM);
            Ks[row][d] = qkv[base + DIM     + h * HD + d];
            Vs[row][d] = qkv[base + 2 * DIM + h * HD + d];
        }
        __syncthreads();

        // S = scale * q . k  (each thread: 16 of this row's 64 columns)
        float sv[16];
        float tmax = -1e30f;
        #pragma unroll
        for (int jj = 0; jj < 16; jj++) {
            int j = c4 + jj * 4;
            float s = 0.f;
            #pragma unroll
            for (int d = 0; d < 32; d++) s += qreg[d] * Ks[j][d];
            s *= scale;
            sv[jj] = s;
            tmax = fmaxf(tmax, s);
        }
        // reduce max across the 4 lanes of this q-row (same warp)
        tmax = fmaxf(tmax, __shfl_xor_sync(0xffffffffu, tmax, 1));
        tmax = fmaxf(tmax, __shfl_xor_sync(0xffffffffu, tmax, 2));
        float m_new = fmaxf(m_run, tmax);
        float corr  = __expf(m_run - m_new);

        float tsum = 0.f;
        #pragma unroll
        for (int jj = 0; jj < 16; jj++) {
            float p = __expf(sv[jj] - m_new);
            Ss[r][c4 + jj * 4] = p;
            tsum += p;
        }
        tsum += __shfl_xor_sync(0xffffffffu, tsum, 1);
        tsum += __shfl_xor_sync(0xffffffffu, tsum, 2);
        l_run = l_run * corr + tsum;
        m_run = m_new;

        #pragma unroll
        for (int i = 0; i < 8; i++) acc[i] *= corr;
        __syncwarp();  // sibling lanes' Ss writes visible (same warp)

        #pragma unroll 4
        for (int j = 0; j < TK; j++) {
            float p = Ss[r][j];
            const float* vrow = &Vs[j][c4 * 8];
            #pragma unroll
            for (int dd = 0; dd < 8; dd++) acc[dd] += p * vrow[dd];
        }
    }

    float inv = 1.f / l_run;
    int n = qt * TQ + r;
    float* op = &out[((size_t)(b * SEQ + n)) * DIM + h * HD + c4 * 8];
    #pragma unroll
    for (int dd = 0; dd < 8; dd++) op[dd] = acc[dd] * inv;
}

// ------------------------------ host launch ---------------------------------
extern "C" void kernel_launch(void* const* d_in, const int* in_sizes, int n_in,
                              void* d_out, int out_size)
{
    // metadata order: x, ln1_g, ln1_b, Wqkv, bqkv, Wo, bo, ln2_g, ln2_b,
    //                 W1, b1, W2, b2, heads
    const float* x     = (const float*)d_in[0];
    const float* ln1_g = (const float*)d_in[1] + LAYER * DIM;
    const float* ln1_b = (const float*)d_in[2] + LAYER * DIM;
    const float* Wqkv  = (const float*)d_in[3] + (size_t)LAYER * DIM * 3 * DIM;
    const float* bqkv  = (const float*)d_in[4] + LAYER * 3 * DIM;
    const float* Wo    = (const float*)d_in[5] + (size_t)LAYER * DIM * DIM;
    const float* bo    = (const float*)d_in[6] + LAYER * DIM;
    const float* ln2_g = (const float*)d_in[7] + LAYER * DIM;
    const float* ln2_b = (const float*)d_in[8] + LAYER * DIM;
    const float* W1    = (const float*)d_in[9] + (size_t)LAYER * DIM * MLPD;
    const float* b1    = (const float*)d_in[10] + LAYER * MLPD;
    const float* W2    = (const float*)d_in[11] + (size_t)LAYER * MLPD * DIM;
    const float* b2    = (const float*)d_in[12] + LAYER * DIM;
    float* out = (float*)d_out;

    float *y, *qkv, *attn, *a, *z, *hbuf;
    cudaGetSymbolAddress((void**)&y,    g_y);
    cudaGetSymbolAddress((void**)&qkv,  g_qkv);
    cudaGetSymbolAddress((void**)&attn, g_attn);
    cudaGetSymbolAddress((void**)&a,    g_a);
    cudaGetSymbolAddress((void**)&z,    g_z);
    cudaGetSymbolAddress((void**)&hbuf, g_h);

    // 1. y = LN1(x)
    ln_kernel<<<ROWS, 256>>>(x, ln1_g, ln1_b, y);

    // 2. qkv = y @ Wqkv + bqkv           [4096 x 768]
    gemm_kernel<0><<<dim3((3 * DIM) / 64, ROWS / 64), 256>>>(
        y, Wqkv, bqkv, nullptr, qkv, ROWS, 3 * DIM, DIM);

    // 3. attention                        [4096 x 256]
    attn_kernel<<<dim3(SEQ / TQ, BATCH * HEADS), 256>>>(qkv, attn);

    // 4. a = attn @ Wo + bo + x           [4096 x 256]
    gemm_kernel<2><<<dim3(DIM / 64, ROWS / 64), 256>>>(
        attn, Wo, bo, x, a, ROWS, DIM, DIM);

    // 5. z = LN2(a)
    ln_kernel<<<ROWS, 256>>>(a, ln2_g, ln2_b, z);

    // 6. h = gelu(z @ W1 + b1)            [4096 x 1024]
    gemm_kernel<1><<<dim3(MLPD / 64, ROWS / 64), 256>>>(
        z, W1, b1, nullptr, hbuf, ROWS, MLPD, DIM);

    // 7. out = h @ W2 + b2 + a            [4096 x 256]
    gemm_kernel<2><<<dim3(DIM / 64, ROWS / 64), 256>>>(
        hbuf, W2, b2, a, out, ROWS, DIM, MLPD);
}

// round 5
// speedup vs baseline: 1.0034x; 1.0034x over previous
#include <cuda_runtime.h>
#include <cuda_bf16.h>
#include <math.h>

// Problem constants (DEPTH=2, but reference only returns last layer's output
// computed from the ORIGINAL x, so we evaluate ONLY layer index 1).
#define BATCH 2
#define SEQ   2048
#define DIM   256
#define MLPD  1024
#define HEADS 8
#define HD    32
#define ROWS  (BATCH*SEQ)          // 4096
#define LAYER 1                    // depth-1

// ------------------------- scratch (device globals) -------------------------
__device__ float g_y   [ROWS*DIM];    // ln1 out
__device__ float g_qkv [ROWS*3*DIM];  // qkv
__device__ float g_attn[ROWS*DIM];    // attention output (pre O-proj)
__device__ float g_a   [ROWS*DIM];    // attn residual
__device__ float g_z   [ROWS*DIM];    // ln2 out
__device__ float g_h   [ROWS*MLPD];   // mlp hidden

// ------------------------------ LayerNorm -----------------------------------
// One block (256 threads) per row of 256 elements.
__global__ void ln_kernel(const float* __restrict__ x,
                          const float* __restrict__ gamma,
                          const float* __restrict__ beta,
                          float* __restrict__ y)
{
    int row = blockIdx.x;
    int tid = threadIdx.x;
    float v = x[(size_t)row * DIM + tid];

    float s = v, sq = v * v;
    #pragma unroll
    for (int o = 16; o; o >>= 1) {
        s  += __shfl_xor_sync(0xffffffffu, s,  o);
        sq += __shfl_xor_sync(0xffffffffu, sq, o);
    }
    __shared__ float red[2][8];
    int w = tid >> 5, l = tid & 31;
    if (l == 0) { red[0][w] = s; red[1][w] = sq; }
    __syncthreads();
    float st = 0.f, sqt = 0.f;
    #pragma unroll
    for (int i = 0; i < 8; i++) { st += red[0][i]; sqt += red[1][i]; }
    float mean = st * (1.0f / DIM);
    float var  = sqt * (1.0f / DIM) - mean * mean;
    float inv  = rsqrtf(var + 1e-5f);
    y[(size_t)row * DIM + tid] = (v - mean) * inv * gamma[tid] + beta[tid];
}

// --------------------------------- GEMM -------------------------------------
// C[M,N] = A[M,K] @ B[K,N] + bias[N]  (+ epilogue)
// EPI: 0 = bias only, 1 = bias + exact GELU, 2 = bias + residual add
// 64x64 block tile, 256 threads, 4x4 microtile, KT=16. M,N multiples of 64,
// K multiple of 16 (true for all four GEMMs here).
template <int EPI>
__global__ void gemm_kernel(const float* __restrict__ A,
                            const float* __restrict__ B,
                            const float* __restrict__ bias,
                            const float* __restrict__ res,
                            float* __restrict__ C,
                            int M, int N, int K)
{
    __shared__ float As[64][17];   // [m][k], padded
    __shared__ float Bs[16][64];   // [k][n], float4-readable

    int tid = threadIdx.x;
    int bm = blockIdx.y * 64;
    int bn = blockIdx.x * 64;

    float acc[4][4];
    #pragma unroll
    for (int i = 0; i < 4; i++)
        #pragma unroll
        for (int j = 0; j < 4; j++) acc[i][j] = 0.f;

    int tx = tid & 15, ty = tid >> 4;

    for (int k0 = 0; k0 < K; k0 += 16) {
        #pragma unroll
        for (int i = 0; i < 4; i++) {
            int li = tid + i * 256;
            int m = li >> 4, kk = li & 15;
            As[m][kk] = A[(size_t)(bm + m) * K + k0 + kk];
        }
        #pragma unroll
        for (int i = 0; i < 4; i++) {
            int li = tid + i * 256;
            int kk = li >> 6, n = li & 63;
            Bs[kk][n] = B[(size_t)(k0 + kk) * N + bn + n];
        }
        __syncthreads();

        #pragma unroll
        for (int kk = 0; kk < 16; kk++) {
            float4 b4 = *(const float4*)&Bs[kk][tx * 4];
            float bv[4] = { b4.x, b4.y, b4.z, b4.w };
            #pragma unroll
            for (int i = 0; i < 4; i++) {
                float av = As[ty * 4 + i][kk];
                #pragma unroll
                for (int j = 0; j < 4; j++) acc[i][j] += av * bv[j];
            }
        }
        __syncthreads();
    }

    #pragma unroll
    for (int i = 0; i < 4; i++) {
        int m = bm + ty * 4 + i;
        #pragma unroll
        for (int j = 0; j < 4; j++) {
            int n = bn + tx * 4 + j;
            float c = acc[i][j] + bias[n];
            if (EPI == 1) {
                // exact GELU: 0.5*x*(1+erf(x/sqrt(2)))
                c = 0.5f * c * (1.0f + erff(c * 0.7071067811865476f));
            } else if (EPI == 2) {
                c += res[(size_t)m * N + n];
            }
            C[(size_t)m * N + n] = c;
        }
    }
}

// ------------------------------ Attention -----------------------------------
// qkv layout: [b, n, comp(3), h(8), hd(32)]  (comp: 0=q, 1=k, 2=v)
// Flash-style online softmax. Block = 64 query rows of one (b,h).
// 256 threads: 4 threads per q-row; each owns 8 of 32 output dims.
#define TQ 64
#define TK 64
__global__ void attn_kernel(const float* __restrict__ qkv,
                            float* __restrict__ out)
{
    __shared__ float Qs[TQ][33];
    __shared__ float Ks[TK][33];
    __shared__ float Vs[TK][32];
    __shared__ float Ss[TQ][TK];

    int bh = blockIdx.y;
    int b  = bh >> 3;
    int h  = bh & 7;
    int qt = blockIdx.x;
    int tid = threadIdx.x;
    int r  = tid >> 2;   // q-row in tile
    int c4 = tid & 3;    // which quarter of dims / which j-phase
    const float scale = 0.17677669529663687f;  // 1/sqrt(32)

    for (int i = tid; i < TQ * 32; i += 256) {
        int row = i >> 5, d = i & 31;
        int n = qt * TQ + row;
        Qs[row][d] = qkv[((size_t)(b * SEQ + n)) * (3 * DIM) + h * HD + d];
    }
    __syncthreads();

    float qreg[32];
    #pragma unroll
    for (int d = 0; d < 32; d++) qreg[d] = Qs[r][d];

    float m_run = -1e30f, l_run = 0.f;
    float acc[8];
    #pragma unroll
    for (int i = 0; i < 8; i++) acc[i] = 0.f;

    for (int kt = 0; kt < SEQ / TK; kt++) {
        __syncthreads();  // previous iteration's Ss/Vs reads complete
        for (int i = tid; i < TK * 32; i += 256) {
            int row = i >> 5, d = i & 31;
            int n = kt * TK + row;
            size_t base = ((size_t)(b * SEQ + n)) * (3 * DIM);
            Ks[row][d] = qkv[base + DIM     + h * HD + d];
            Vs[row][d] = qkv[base + 2 * DIM + h * HD + d];
        }
        __syncthreads();

        // S = scale * q . k  (each thread: 16 of this row's 64 columns)
        float sv[16];
        float tmax = -1e30f;
        #pragma unroll
        for (int jj = 0; jj < 16; jj++) {
            int j = c4 + jj * 4;
            float s = 0.f;
            #pragma unroll
            for (int d = 0; d < 32; d++) s += qreg[d] * Ks[j][d];
            s *= scale;
            sv[jj] = s;
            tmax = fmaxf(tmax, s);
        }
        // reduce max across the 4 lanes of this q-row (same warp)
        tmax = fmaxf(tmax, __shfl_xor_sync(0xffffffffu, tmax, 1));
        tmax = fmaxf(tmax, __shfl_xor_sync(0xffffffffu, tmax, 2));
        float m_new = fmaxf(m_run, tmax);
        float corr  = __expf(m_run - m_new);

        float tsum = 0.f;
        #pragma unroll
        for (int jj = 0; jj < 16; jj++) {
            float p = __expf(sv[jj] - m_new);
            Ss[r][c4 + jj * 4] = p;
            tsum += p;
        }
        tsum += __shfl_xor_sync(0xffffffffu, tsum, 1);
        tsum += __shfl_xor_sync(0xffffffffu, tsum, 2);
        l_run = l_run * corr + tsum;
        m_run = m_new;

        #pragma unroll
        for (int i = 0; i < 8; i++) acc[i] *= corr;
        __syncwarp();  // sibling lanes' Ss writes visible (same warp)

        #pragma unroll 4
        for (int j = 0; j < TK; j++) {
            float p = Ss[r][j];
            const float* vrow = &Vs[j][c4 * 8];
            #pragma unroll
            for (int dd = 0; dd < 8; dd++) acc[dd] += p * vrow[dd];
        }
    }

    float inv = 1.f / l_run;
    int n = qt * TQ + r;
    float* op = &out[((size_t)(b * SEQ + n)) * DIM + h * HD + c4 * 8];
    #pragma unroll
    for (int dd = 0; dd < 8; dd++) op[dd] = acc[dd] * inv;
}

// ------------------------------ host launch ---------------------------------
extern "C" void kernel_launch(void* const* d_in, const int* in_sizes, int n_in,
                              void* d_out, int out_size)
{
    // metadata order: x, ln1_g, ln1_b, Wqkv, bqkv, Wo, bo, ln2_g, ln2_b,
    //                 W1, b1, W2, b2, heads
    const float* x     = (const float*)d_in[0];
    const float* ln1_g = (const float*)d_in[1] + LAYER * DIM;
    const float* ln1_b = (const float*)d_in[2] + LAYER * DIM;
    const float* Wqkv  = (const float*)d_in[3] + (size_t)LAYER * DIM * 3 * DIM;
    const float* bqkv  = (const float*)d_in[4] + LAYER * 3 * DIM;
    const float* Wo    = (const float*)d_in[5] + (size_t)LAYER * DIM * DIM;
    const float* bo    = (const float*)d_in[6] + LAYER * DIM;
    const float* ln2_g = (const float*)d_in[7] + LAYER * DIM;
    const float* ln2_b = (const float*)d_in[8] + LAYER * DIM;
    const float* W1    = (const float*)d_in[9] + (size_t)LAYER * DIM * MLPD;
    const float* b1    = (const float*)d_in[10] + LAYER * MLPD;
    const float* W2    = (const float*)d_in[11] + (size_t)LAYER * MLPD * DIM;
    const float* b2    = (const float*)d_in[12] + LAYER * DIM;
    float* out = (float*)d_out;

    float *y, *qkv, *attn, *a, *z, *hbuf;
    cudaGetSymbolAddress((void**)&y,    g_y);
    cudaGetSymbolAddress((void**)&qkv,  g_qkv);
    cudaGetSymbolAddress((void**)&attn, g_attn);
    cudaGetSymbolAddress((void**)&a,    g_a);
    cudaGetSymbolAddress((void**)&z,    g_z);
    cudaGetSymbolAddress((void**)&hbuf, g_h);

    // 1. y = LN1(x)
    ln_kernel<<<ROWS, 256>>>(x, ln1_g, ln1_b, y);

    // 2. qkv = y @ Wqkv + bqkv           [4096 x 768]
    gemm_kernel<0><<<dim3((3 * DIM) / 64, ROWS / 64), 256>>>(
        y, Wqkv, bqkv, nullptr, qkv, ROWS, 3 * DIM, DIM);

    // 3. attention                        [4096 x 256]
    attn_kernel<<<dim3(SEQ / TQ, BATCH * HEADS), 256>>>(qkv, attn);

    // 4. a = attn @ Wo + bo + x           [4096 x 256]
    gemm_kernel<2><<<dim3(DIM / 64, ROWS / 64), 256>>>(
        attn, Wo, bo, x, a, ROWS, DIM, DIM);

    // 5. z = LN2(a)
    ln_kernel<<<ROWS, 256>>>(a, ln2_g, ln2_b, z);

    // 6. h = gelu(z @ W1 + b1)            [4096 x 1024]
    gemm_kernel<1><<<dim3(MLPD / 64, ROWS / 64), 256>>>(
        z, W1, b1, nullptr, hbuf, ROWS, MLPD, DIM);

    // 7. out = h @ W2 + b2 + a            [4096 x 256]
    gemm_kernel<2><<<dim3(DIM / 64, ROWS / 64), 256>>>(
        hbuf, W2, b2, a, out, ROWS, DIM, MLPD);
}